// round 13
// baseline (speedup 1.0000x reference)
#include <cuda_runtime.h>
#include <math_constants.h>
#include <cstdint>

#define Bb   16
#define Nn   2048
#define Cc   10
#define KK   16
#define BNT  (Bb*Nn)        // 32768 nodes
#define EDG  (BNT*KK)       // 524288 edges

// ---------------- scratch (device globals: no allocation allowed) ----------
__device__ int   g_nbr[EDG];
__device__ int   g_deg[BNT];
__device__ int   g_off[BNT];
__device__ int   g_cur[BNT];
__device__ int   g_rev[EDG];
__device__ float g_h [BNT*128];     // Acat0 (stride 20)
__device__ float g_hb[BNT*128];     // final H (stride 64)
__device__ float g_a [BNT*256];     // h1 / h3 (stride 128)
__device__ float g_b [BNT*256];     // h2 (stride 128)

// ---------------- kNN v4: 4 threads per query ------------------------------
// Block = 256 threads = 64 queries x 4 quarters. Quarter q scans candidate
// groups j0 = q*4, step 16 (disjoint -> no duplicate candidates). Each
// quarter keeps its own 16-best (sees 512 candidates >> 16, so lists
// saturate and the final merge is exact).
__global__ void __launch_bounds__(256) knn_kernel(const float* __restrict__ x) {
    __shared__ float sn[Nn];
    __shared__ float sd[KK][256];
    __shared__ int   si[KK][256];
    int t    = threadIdx.x;
    int qi   = t & 63;
    int quarter = t >> 6;
    int node = blockIdx.x * 64 + qi;
    int b    = node >> 11;
    int i    = node & 2047;
    const float*  xb  = x + (size_t)b * Nn * Cc;
    const float4* xb4 = (const float4*)xb;

    for (int j = t; j < Nn; j += 256) {
        float s = 0.f;
#pragma unroll
        for (int c = 0; c < Cc; c++) { float v = xb[j * Cc + c]; s = fmaf(v, v, s); }
        sn[j] = s;
    }
    float xi[Cc];
#pragma unroll
    for (int c = 0; c < Cc; c++) xi[c] = xb[i * Cc + c];
#pragma unroll
    for (int r = 0; r < KK; r++) { sd[r][t] = CUDART_INF_F; si[r][t] = 0; }
    __syncthreads();
    float x2i = sn[i];

    float cut = CUDART_INF_F;
    int   cutpos = 0;

    for (int j0 = quarter * 4; j0 < Nn; j0 += 16) {
        float v[40];
#pragma unroll
        for (int q = 0; q < 10; q++) {
            float4 t4 = xb4[(j0 * 10) / 4 + q];
            v[q*4+0] = t4.x; v[q*4+1] = t4.y; v[q*4+2] = t4.z; v[q*4+3] = t4.w;
        }
#pragma unroll
        for (int jj = 0; jj < 4; jj++) {
            int j = j0 + jj;
            float dot = 0.f;
#pragma unroll
            for (int c = 0; c < Cc; c++) dot = fmaf(xi[c], v[jj * 10 + c], dot);
            float d2 = fmaf(-2.f, dot, x2i + sn[j]);
            if (j != i && d2 < cut) {
                sd[cutpos][t] = d2; si[cutpos][t] = j;
                float m = sd[0][t]; int mp = 0;
#pragma unroll
                for (int r = 1; r < KK; r++) {
                    float dr = sd[r][t];
                    if (dr > m) { m = dr; mp = r; }
                }
                cut = m; cutpos = mp;
            }
        }
    }
    __syncthreads();

    if (quarter == 0) {
        // merge the other three quarters' lists (exact: unsorted k-best)
#pragma unroll
        for (int p = 1; p < 4; p++) {
#pragma unroll
            for (int r = 0; r < KK; r++) {
                float d2 = sd[r][t + p * 64];
                int   j  = si[r][t + p * 64];
                if (d2 < cut) {
                    sd[cutpos][t] = d2; si[cutpos][t] = j;
                    float m = sd[0][t]; int mp = 0;
#pragma unroll
                    for (int rr = 1; rr < KK; rr++) {
                        float dr = sd[rr][t];
                        if (dr > m) { m = dr; mp = rr; }
                    }
                    cut = m; cutpos = mp;
                }
            }
        }
        int base = node * KK;
#pragma unroll
        for (int r = 0; r < KK; r++) {
            int nb = (b << 11) + si[r][t];
            g_nbr[base + r] = nb;
            atomicAdd(&g_deg[nb], 1);
        }
    }
}

// ---------------- exclusive scan v3: 32 elems/thread, one pass --------------
__global__ void scan_kernel() {
    __shared__ int wsum[32];
    int t = threadIdx.x, lane = t & 31, w = t >> 5;
    int base_i = t * 32;
    int loc[32];
    int s = 0;
#pragma unroll
    for (int q = 0; q < 8; q++) {
        int4 v = *(const int4*)&g_deg[base_i + q * 4];
        loc[q*4+0] = s; s += v.x;
        loc[q*4+1] = s; s += v.y;
        loc[q*4+2] = s; s += v.z;
        loc[q*4+3] = s; s += v.w;
    }
    int inc = s;
#pragma unroll
    for (int o = 1; o < 32; o <<= 1) {
        int n = __shfl_up_sync(0xffffffffu, inc, o);
        if (lane >= o) inc += n;
    }
    if (lane == 31) wsum[w] = inc;
    __syncthreads();
    if (w == 0) {
        int v2 = wsum[lane];
#pragma unroll
        for (int o = 1; o < 32; o <<= 1) {
            int n = __shfl_up_sync(0xffffffffu, v2, o);
            if (lane >= o) v2 += n;
        }
        wsum[lane] = v2;
    }
    __syncthreads();
    int base = ((w > 0) ? wsum[w - 1] : 0) + inc - s;
#pragma unroll
    for (int q = 0; q < 8; q++) {
        int4 o4 = make_int4(base + loc[q*4+0], base + loc[q*4+1],
                            base + loc[q*4+2], base + loc[q*4+3]);
        *(int4*)&g_off[base_i + q * 4] = o4;
        *(int4*)&g_cur[base_i + q * 4] = o4;
    }
}

__global__ void fill_kernel() {
    int e = blockIdx.x * blockDim.x + threadIdx.x;
    if (e >= EDG) return;
    int i = e >> 4;
    int v = g_nbr[e];
    int pos = atomicAdd(&g_cur[v], 1);
    g_rev[pos] = i;
}

// ---------------- aggx v2: edge-parallel, warp per 2 nodes ------------------
// Lanes 0-15 -> node v0's reverse edges, lanes 16-31 -> node v1's. Each lane
// accumulates one edge's 10 channels; width-16 butterfly reduces.
__global__ void aggx_kernel(const float* __restrict__ x, float* __restrict__ acat) {
    int warp = threadIdx.x >> 5, lane = threadIdx.x & 31;
    int vbase = blockIdx.x * 16 + warp * 2;
    int grp = lane >> 4;
    int el  = lane & 15;
    int v = vbase + grp;
    int off = g_off[v], deg = g_deg[v];
    float acc[Cc];
#pragma unroll
    for (int c = 0; c < Cc; c++) acc[c] = 0.f;
    for (int e = el; e < deg; e += 16) {
        int u = __ldg(&g_rev[off + e]);
        const float* xu = &x[(size_t)u * Cc];
#pragma unroll
        for (int c = 0; c < Cc; c++) acc[c] += xu[c];
    }
#pragma unroll
    for (int o = 8; o >= 1; o >>= 1) {
#pragma unroll
        for (int c = 0; c < Cc; c++)
            acc[c] += __shfl_down_sync(0xffffffffu, acc[c], o, 16);
    }
    if (el == 0) {
#pragma unroll
        for (int c = 0; c < Cc; c++)
            acat[(size_t)v * 20 + 10 + c] = acc[c];
    }
    // root copy: 20 lanes write the 2 nodes' raw features
    if (lane < 2 * Cc) {
        int vv = vbase + (lane >= Cc);
        int cc = lane % Cc;
        acat[(size_t)vv * 20 + cc] = x[(size_t)vv * Cc + cc];
    }
}

// ---------------- tf32 helpers ----------------------------------------------
__device__ __forceinline__ float f2tf_f(float f) {
    uint32_t u;
    asm("cvt.rna.tf32.f32 %0, %1;" : "=r"(u) : "f"(f));
    return __uint_as_float(u);
}
__device__ __forceinline__ uint32_t f2tf(float f) {
    uint32_t u;
    asm("cvt.rna.tf32.f32 %0, %1;" : "=r"(u) : "f"(f));
    return u;
}

#define GLDA 17

// ---------------- generic tf32 GEMM (layer 0): Out = relu(A@[wo;wr]+b) ------
__global__ void __launch_bounds__(256, 2) gemm_tf32_kernel(
        const float* __restrict__ A, int lda, int K, int Khalf,
        const float* __restrict__ wo, const float* __restrict__ wr, int P,
        const float* __restrict__ bias, float* __restrict__ Out, int ldo,
        int do_relu) {
    __shared__ float As[128 * GLDA];
    __shared__ float Ws[128 * GLDA];
    int bm  = blockIdx.x * 128;
    int tid = threadIdx.x;
    int r2  = tid >> 1;
    int kh  = (tid & 1) * 8;
    int warp = tid >> 5, lane = tid & 31;
    int wm = warp & 3, wn = warp >> 2;
    int g  = lane >> 2, t4 = lane & 3;

    float acc[2][8][4];
#pragma unroll
    for (int mt = 0; mt < 2; mt++)
#pragma unroll
        for (int nt = 0; nt < 8; nt++)
#pragma unroll
            for (int e = 0; e < 4; e++) acc[mt][nt][e] = 0.f;

    for (int k0 = 0; k0 < K; k0 += 16) {
        const float* Ap = &A[(size_t)(bm + r2) * lda + k0 + kh];
        if (k0 + kh + 8 <= K) {
            float4 v0 = *(const float4*)Ap;
            float4 v1 = *(const float4*)(Ap + 4);
            As[r2 * GLDA + kh + 0] = f2tf_f(v0.x);
            As[r2 * GLDA + kh + 1] = f2tf_f(v0.y);
            As[r2 * GLDA + kh + 2] = f2tf_f(v0.z);
            As[r2 * GLDA + kh + 3] = f2tf_f(v0.w);
            As[r2 * GLDA + kh + 4] = f2tf_f(v1.x);
            As[r2 * GLDA + kh + 5] = f2tf_f(v1.y);
            As[r2 * GLDA + kh + 6] = f2tf_f(v1.z);
            As[r2 * GLDA + kh + 7] = f2tf_f(v1.w);
        } else {
#pragma unroll
            for (int q = 0; q < 8; q++) {
                int kk = k0 + kh + q;
                As[r2 * GLDA + kh + q] = (kk < K) ? f2tf_f(Ap[q]) : 0.f;
            }
        }
#pragma unroll
        for (int q = 0; q < 8; q++) {
            int kk = k0 + kh + q;
            float v = 0.f;
            if (kk < K && r2 < P)
                v = (kk < Khalf) ? wo[(size_t)kk * P + r2]
                                 : wr[(size_t)(kk - Khalf) * P + r2];
            Ws[r2 * GLDA + kh + q] = f2tf_f(v);
        }
        __syncthreads();
#pragma unroll
        for (int ks = 0; ks < 16; ks += 8) {
            uint32_t a[2][4], bfr[8][2];
#pragma unroll
            for (int mt = 0; mt < 2; mt++) {
                int row = wm * 32 + mt * 16;
                a[mt][0] = __float_as_uint(As[(row + g    ) * GLDA + ks + t4    ]);
                a[mt][1] = __float_as_uint(As[(row + g + 8) * GLDA + ks + t4    ]);
                a[mt][2] = __float_as_uint(As[(row + g    ) * GLDA + ks + t4 + 4]);
                a[mt][3] = __float_as_uint(As[(row + g + 8) * GLDA + ks + t4 + 4]);
            }
#pragma unroll
            for (int nt = 0; nt < 8; nt++) {
                int col = wn * 64 + nt * 8;
                bfr[nt][0] = __float_as_uint(Ws[(col + g) * GLDA + ks + t4    ]);
                bfr[nt][1] = __float_as_uint(Ws[(col + g) * GLDA + ks + t4 + 4]);
            }
#pragma unroll
            for (int mt = 0; mt < 2; mt++)
#pragma unroll
                for (int nt = 0; nt < 8; nt++) {
                    asm volatile(
                        "mma.sync.aligned.m16n8k8.row.col.f32.tf32.tf32.f32 "
                        "{%0,%1,%2,%3}, {%4,%5,%6,%7}, {%8,%9}, {%0,%1,%2,%3};"
                        : "+f"(acc[mt][nt][0]), "+f"(acc[mt][nt][1]),
                          "+f"(acc[mt][nt][2]), "+f"(acc[mt][nt][3])
                        : "r"(a[mt][0]), "r"(a[mt][1]), "r"(a[mt][2]), "r"(a[mt][3]),
                          "r"(bfr[nt][0]), "r"(bfr[nt][1]));
                }
        }
        __syncthreads();
    }

#pragma unroll
    for (int nt = 0; nt < 8; nt++) {
        int col = wn * 64 + nt * 8 + 2 * t4;
        if (col >= P) continue;
        float b0 = bias[col], b1 = bias[col + 1];
#pragma unroll
        for (int mt = 0; mt < 2; mt++) {
            int row = bm + wm * 32 + mt * 16 + g;
            float o0 = acc[mt][nt][0] + b0;
            float o1 = acc[mt][nt][1] + b1;
            float o2 = acc[mt][nt][2] + b0;
            float o3 = acc[mt][nt][3] + b1;
            if (do_relu) {
                o0 = fmaxf(o0, 0.f); o1 = fmaxf(o1, 0.f);
                o2 = fmaxf(o2, 0.f); o3 = fmaxf(o3, 0.f);
            }
            *(float2*)&Out[(size_t)row * ldo + col]       = make_float2(o0, o1);
            *(float2*)&Out[(size_t)(row + 8) * ldo + col] = make_float2(o2, o3);
        }
    }
}

// ---------------- fused gather+GEMM (layers 1-3) -----------------------------
#define FLDT 132
#define FUSED_SMEM ((128 * FLDT + 2 * 128 * GLDA) * 4)

__global__ void __launch_bounds__(256, 2) gemm_fused_kernel(
        const float* __restrict__ h,
        const float* __restrict__ wo, const float* __restrict__ wr, int P,
        const float* __restrict__ bias, float* __restrict__ Out, int ldo,
        int do_relu) {
    extern __shared__ float sm[];
    float* agg = sm;                       // [128][FLDT]
    float* As  = sm + 128 * FLDT;          // [128][GLDA]
    float* Ws  = As + 128 * GLDA;          // [128][GLDA]
    int bm  = blockIdx.x * 128;
    int tid = threadIdx.x;
    int warp = tid >> 5, lane = tid & 31;

    // ---- gather neighbor sums, 4-way unrolled for MLP ----
#pragma unroll 1
    for (int s = 0; s < 16; s++) {
        int r = warp * 16 + s;
        int v = bm + r;
        int c4 = lane * 4;
        int off = g_off[v];
        int deg = g_deg[v];
        float4 a0 = make_float4(0.f, 0.f, 0.f, 0.f);
        float4 a1 = a0, a2 = a0, a3 = a0;
        int q = off, qe = off + deg;
        for (; q + 4 <= qe; q += 4) {
            int u0 = __ldg(&g_rev[q]);
            int u1 = __ldg(&g_rev[q + 1]);
            int u2 = __ldg(&g_rev[q + 2]);
            int u3 = __ldg(&g_rev[q + 3]);
            float4 t0 = *(const float4*)&h[(size_t)u0 * 128 + c4];
            float4 t1 = *(const float4*)&h[(size_t)u1 * 128 + c4];
            float4 t2 = *(const float4*)&h[(size_t)u2 * 128 + c4];
            float4 t3 = *(const float4*)&h[(size_t)u3 * 128 + c4];
            a0.x += t0.x; a0.y += t0.y; a0.z += t0.z; a0.w += t0.w;
            a1.x += t1.x; a1.y += t1.y; a1.z += t1.z; a1.w += t1.w;
            a2.x += t2.x; a2.y += t2.y; a2.z += t2.z; a2.w += t2.w;
            a3.x += t3.x; a3.y += t3.y; a3.z += t3.z; a3.w += t3.w;
        }
        for (; q < qe; q++) {
            int u = __ldg(&g_rev[q]);
            float4 t0 = *(const float4*)&h[(size_t)u * 128 + c4];
            a0.x += t0.x; a0.y += t0.y; a0.z += t0.z; a0.w += t0.w;
        }
        float4 acc;
        acc.x = (a0.x + a1.x) + (a2.x + a3.x);
        acc.y = (a0.y + a1.y) + (a2.y + a3.y);
        acc.z = (a0.z + a1.z) + (a2.z + a3.z);
        acc.w = (a0.w + a1.w) + (a2.w + a3.w);
        float4 ta;
        ta.x = f2tf_f(acc.x); ta.y = f2tf_f(acc.y);
        ta.z = f2tf_f(acc.z); ta.w = f2tf_f(acc.w);
        *(float4*)&agg[r * FLDT + c4] = ta;
    }
    __syncthreads();

    int r2 = tid >> 1;
    int kh = (tid & 1) * 8;
    int wm = warp & 3, wn = warp >> 2;
    int g  = lane >> 2, t4 = lane & 3;

    float acc[2][8][4];
#pragma unroll
    for (int mt = 0; mt < 2; mt++)
#pragma unroll
        for (int nt = 0; nt < 8; nt++)
#pragma unroll
            for (int e = 0; e < 4; e++) acc[mt][nt][e] = 0.f;

    // ---- left K-half: root features from global h (staged) ----
    for (int k0 = 0; k0 < 128; k0 += 16) {
        const float* Ap = &h[(size_t)(bm + r2) * 128 + k0 + kh];
        float4 v0 = *(const float4*)Ap;
        float4 v1 = *(const float4*)(Ap + 4);
        As[r2 * GLDA + kh + 0] = f2tf_f(v0.x);
        As[r2 * GLDA + kh + 1] = f2tf_f(v0.y);
        As[r2 * GLDA + kh + 2] = f2tf_f(v0.z);
        As[r2 * GLDA + kh + 3] = f2tf_f(v0.w);
        As[r2 * GLDA + kh + 4] = f2tf_f(v1.x);
        As[r2 * GLDA + kh + 5] = f2tf_f(v1.y);
        As[r2 * GLDA + kh + 6] = f2tf_f(v1.z);
        As[r2 * GLDA + kh + 7] = f2tf_f(v1.w);
#pragma unroll
        for (int q = 0; q < 8; q++) {
            int kk = k0 + kh + q;
            float v = (r2 < P) ? wo[(size_t)kk * P + r2] : 0.f;
            Ws[r2 * GLDA + kh + q] = f2tf_f(v);
        }
        __syncthreads();
#pragma unroll
        for (int ks = 0; ks < 16; ks += 8) {
            uint32_t a[2][4], bfr[8][2];
#pragma unroll
            for (int mt = 0; mt < 2; mt++) {
                int row = wm * 32 + mt * 16;
                a[mt][0] = __float_as_uint(As[(row + g    ) * GLDA + ks + t4    ]);
                a[mt][1] = __float_as_uint(As[(row + g + 8) * GLDA + ks + t4    ]);
                a[mt][2] = __float_as_uint(As[(row + g    ) * GLDA + ks + t4 + 4]);
                a[mt][3] = __float_as_uint(As[(row + g + 8) * GLDA + ks + t4 + 4]);
            }
#pragma unroll
            for (int nt = 0; nt < 8; nt++) {
                int col = wn * 64 + nt * 8;
                bfr[nt][0] = __float_as_uint(Ws[(col + g) * GLDA + ks + t4    ]);
                bfr[nt][1] = __float_as_uint(Ws[(col + g) * GLDA + ks + t4 + 4]);
            }
#pragma unroll
            for (int mt = 0; mt < 2; mt++)
#pragma unroll
                for (int nt = 0; nt < 8; nt++) {
                    asm volatile(
                        "mma.sync.aligned.m16n8k8.row.col.f32.tf32.tf32.f32 "
                        "{%0,%1,%2,%3}, {%4,%5,%6,%7}, {%8,%9}, {%0,%1,%2,%3};"
                        : "+f"(acc[mt][nt][0]), "+f"(acc[mt][nt][1]),
                          "+f"(acc[mt][nt][2]), "+f"(acc[mt][nt][3])
                        : "r"(a[mt][0]), "r"(a[mt][1]), "r"(a[mt][2]), "r"(a[mt][3]),
                          "r"(bfr[nt][0]), "r"(bfr[nt][1]));
                }
        }
        __syncthreads();
    }

    // ---- right K-half: aggregated features from smem (direct fragments) ----
    for (int k0 = 0; k0 < 128; k0 += 16) {
#pragma unroll
        for (int q = 0; q < 8; q++) {
            int kk = k0 + kh + q;
            float v = (r2 < P) ? wr[(size_t)kk * P + r2] : 0.f;
            Ws[r2 * GLDA + kh + q] = f2tf_f(v);
        }
        __syncthreads();
#pragma unroll
        for (int ks = 0; ks < 16; ks += 8) {
            int kb = k0 + ks;
            uint32_t a[2][4], bfr[8][2];
#pragma unroll
            for (int mt = 0; mt < 2; mt++) {
                int row = wm * 32 + mt * 16;
                a[mt][0] = __float_as_uint(agg[(row + g    ) * FLDT + kb + t4    ]);
                a[mt][1] = __float_as_uint(agg[(row + g + 8) * FLDT + kb + t4    ]);
                a[mt][2] = __float_as_uint(agg[(row + g    ) * FLDT + kb + t4 + 4]);
                a[mt][3] = __float_as_uint(agg[(row + g + 8) * FLDT + kb + t4 + 4]);
            }
#pragma unroll
            for (int nt = 0; nt < 8; nt++) {
                int col = wn * 64 + nt * 8;
                bfr[nt][0] = __float_as_uint(Ws[(col + g) * GLDA + ks + t4    ]);
                bfr[nt][1] = __float_as_uint(Ws[(col + g) * GLDA + ks + t4 + 4]);
            }
#pragma unroll
            for (int mt = 0; mt < 2; mt++)
#pragma unroll
                for (int nt = 0; nt < 8; nt++) {
                    asm volatile(
                        "mma.sync.aligned.m16n8k8.row.col.f32.tf32.tf32.f32 "
                        "{%0,%1,%2,%3}, {%4,%5,%6,%7}, {%8,%9}, {%0,%1,%2,%3};"
                        : "+f"(acc[mt][nt][0]), "+f"(acc[mt][nt][1]),
                          "+f"(acc[mt][nt][2]), "+f"(acc[mt][nt][3])
                        : "r"(a[mt][0]), "r"(a[mt][1]), "r"(a[mt][2]), "r"(a[mt][3]),
                          "r"(bfr[nt][0]), "r"(bfr[nt][1]));
                }
        }
        __syncthreads();
    }

    // ---- epilogue: bias + optional relu ----
#pragma unroll
    for (int nt = 0; nt < 8; nt++) {
        int col = wn * 64 + nt * 8 + 2 * t4;
        if (col >= P) continue;
        float b0 = bias[col], b1 = bias[col + 1];
#pragma unroll
        for (int mt = 0; mt < 2; mt++) {
            int row = bm + wm * 32 + mt * 16 + g;
            float o0 = acc[mt][nt][0] + b0;
            float o1 = acc[mt][nt][1] + b1;
            float o2 = acc[mt][nt][2] + b0;
            float o3 = acc[mt][nt][3] + b1;
            if (do_relu) {
                o0 = fmaxf(o0, 0.f); o1 = fmaxf(o1, 0.f);
                o2 = fmaxf(o2, 0.f); o3 = fmaxf(o3, 0.f);
            }
            *(float2*)&Out[(size_t)row * ldo + col]       = make_float2(o0, o1);
            *(float2*)&Out[(size_t)(row + 8) * ldo + col] = make_float2(o2, o3);
        }
    }
}

// ---------------- final syrk (tf32 tensor cores, symmetric) ------------------
#define SYRK_LD  68
#define SYRK_SMEM (2 * 128 * SYRK_LD * 4)
#define TLDT 129

__global__ void __launch_bounds__(256, 2) final_syrk_kernel(
        const float* __restrict__ H, float* __restrict__ out) {
    extern __shared__ float smem[];
    float* As = smem;
    float* Bs = smem + 128 * SYRK_LD;
    int b = blockIdx.y;

    int r = blockIdx.x, bi = 0;
    while (r >= 16 - bi) { r -= 16 - bi; bi++; }
    int bj = bi + r;
    int i0 = bi * 128;
    int j0 = bj * 128;

    const float* Hb = H + (size_t)b * Nn * 64;
    int tid = threadIdx.x;

#pragma unroll
    for (int q = 0; q < 8; q++) {
        int f = q * 256 + tid;
        int rr = f >> 4;
        int c = (f & 15) * 4;
        float4 va = *(const float4*)&Hb[(size_t)(i0 + rr) * 64 + c];
        float4 vb = *(const float4*)&Hb[(size_t)(j0 + rr) * 64 + c];
        float4 ta, tb;
        ta.x = __uint_as_float(f2tf(va.x)); ta.y = __uint_as_float(f2tf(va.y));
        ta.z = __uint_as_float(f2tf(va.z)); ta.w = __uint_as_float(f2tf(va.w));
        tb.x = __uint_as_float(f2tf(vb.x)); tb.y = __uint_as_float(f2tf(vb.y));
        tb.z = __uint_as_float(f2tf(vb.z)); tb.w = __uint_as_float(f2tf(vb.w));
        *(float4*)&As[rr * SYRK_LD + c] = ta;
        *(float4*)&Bs[rr * SYRK_LD + c] = tb;
    }
    __syncthreads();

    int warp = tid >> 5, lane = tid & 31;
    int wm = warp & 3;
    int wn = warp >> 2;
    int g  = lane >> 2;
    int t  = lane & 3;

    float acc[2][8][4];
#pragma unroll
    for (int mt = 0; mt < 2; mt++)
#pragma unroll
        for (int nt = 0; nt < 8; nt++)
#pragma unroll
            for (int e = 0; e < 4; e++) acc[mt][nt][e] = 0.f;

#pragma unroll
    for (int ks = 0; ks < 8; ks++) {
        int k0 = ks * 8;
        uint32_t a[2][4], bf[8][2];
#pragma unroll
        for (int mt = 0; mt < 2; mt++) {
            int row = wm * 32 + mt * 16;
            a[mt][0] = __float_as_uint(As[(row + g    ) * SYRK_LD + k0 + t    ]);
            a[mt][1] = __float_as_uint(As[(row + g + 8) * SYRK_LD + k0 + t    ]);
            a[mt][2] = __float_as_uint(As[(row + g    ) * SYRK_LD + k0 + t + 4]);
            a[mt][3] = __float_as_uint(As[(row + g + 8) * SYRK_LD + k0 + t + 4]);
        }
#pragma unroll
        for (int nt = 0; nt < 8; nt++) {
            int col = wn * 64 + nt * 8;
            bf[nt][0] = __float_as_uint(Bs[(col + g) * SYRK_LD + k0 + t    ]);
            bf[nt][1] = __float_as_uint(Bs[(col + g) * SYRK_LD + k0 + t + 4]);
        }
#pragma unroll
        for (int mt = 0; mt < 2; mt++)
#pragma unroll
            for (int nt = 0; nt < 8; nt++) {
                asm volatile(
                    "mma.sync.aligned.m16n8k8.row.col.f32.tf32.tf32.f32 "
                    "{%0,%1,%2,%3}, {%4,%5,%6,%7}, {%8,%9}, {%0,%1,%2,%3};"
                    : "+f"(acc[mt][nt][0]), "+f"(acc[mt][nt][1]),
                      "+f"(acc[mt][nt][2]), "+f"(acc[mt][nt][3])
                    : "r"(a[mt][0]), "r"(a[mt][1]), "r"(a[mt][2]), "r"(a[mt][3]),
                      "r"(bf[nt][0]), "r"(bf[nt][1]));
            }
    }

    float* ob = out + (size_t)b * Nn * Nn;

#pragma unroll
    for (int mt = 0; mt < 2; mt++)
#pragma unroll
        for (int nt = 0; nt < 8; nt++) {
            int row = i0 + wm * 32 + mt * 16 + g;
            int col = j0 + wn * 64 + nt * 8 + 2 * t;
            float2 lo = make_float2(acc[mt][nt][0], acc[mt][nt][1]);
            float2 hi = make_float2(acc[mt][nt][2], acc[mt][nt][3]);
            *(float2*)&ob[(size_t)row * Nn + col]       = lo;
            *(float2*)&ob[(size_t)(row + 8) * Nn + col] = hi;
        }

    if (bi != bj) {
        __syncthreads();
        float* trans = smem;  // [128][TLDT]
#pragma unroll
        for (int mt = 0; mt < 2; mt++)
#pragma unroll
            for (int nt = 0; nt < 8; nt++) {
                int r0 = wm * 32 + mt * 16 + g;
                int c0 = wn * 64 + nt * 8 + 2 * t;
                trans[r0 * TLDT + c0]           = acc[mt][nt][0];
                trans[r0 * TLDT + c0 + 1]       = acc[mt][nt][1];
                trans[(r0 + 8) * TLDT + c0]     = acc[mt][nt][2];
                trans[(r0 + 8) * TLDT + c0 + 1] = acc[mt][nt][3];
            }
        __syncthreads();
#pragma unroll 1
        for (int s = 0; s < 16; s++) {
            int jr = warp * 16 + s;
#pragma unroll
            for (int q = 0; q < 4; q++) {
                int ic = q * 32 + lane;
                float v = trans[ic * TLDT + jr];
                ob[(size_t)(j0 + jr) * Nn + i0 + ic] = v;
            }
        }
    }
}

// ---------------- launch ----------------------------------------------------
extern "C" void kernel_launch(void* const* d_in, const int* in_sizes, int n_in,
                              void* d_out, int out_size) {
    const float* x   = (const float*)d_in[0];
    const float* wr0 = (const float*)d_in[1];
    const float* wo0 = (const float*)d_in[2];
    const float* bb0 = (const float*)d_in[3];
    const float* wr1 = (const float*)d_in[4];
    const float* wo1 = (const float*)d_in[5];
    const float* bb1 = (const float*)d_in[6];
    const float* wr2 = (const float*)d_in[7];
    const float* wo2 = (const float*)d_in[8];
    const float* bb2 = (const float*)d_in[9];
    const float* wr3 = (const float*)d_in[10];
    const float* wo3 = (const float*)d_in[11];
    const float* bb3 = (const float*)d_in[12];
    float* out = (float*)d_out;

    float *acat0, *H, *h13, *h2;
    int *degp;
    cudaGetSymbolAddress((void**)&acat0, g_h);
    cudaGetSymbolAddress((void**)&H,     g_hb);
    cudaGetSymbolAddress((void**)&h13,   g_a);
    cudaGetSymbolAddress((void**)&h2,    g_b);
    cudaGetSymbolAddress((void**)&degp,  g_deg);

    cudaFuncSetAttribute(final_syrk_kernel,
                         cudaFuncAttributeMaxDynamicSharedMemorySize, SYRK_SMEM);
    cudaFuncSetAttribute(gemm_fused_kernel,
                         cudaFuncAttributeMaxDynamicSharedMemorySize, FUSED_SMEM);

    // graph construction
    cudaMemsetAsync(degp, 0, BNT * sizeof(int), 0);
    knn_kernel<<<BNT / 64, 256>>>(x);
    scan_kernel<<<1, 1024>>>();
    fill_kernel<<<(EDG + 255) / 256, 256>>>();

    // layer 0: Acat0 = [x | agg(x)] (K=20) -> h1 [BNT][128]
    aggx_kernel<<<BNT / 16, 256>>>(x, acat0);
    gemm_tf32_kernel<<<BNT / 128, 256>>>(acat0, 20, 20, 10, wo0, wr0, 128,
                                         bb0, h13, 128, 1);
    // layers 1-3: fused gather + GEMM
    gemm_fused_kernel<<<BNT / 128, 256, FUSED_SMEM>>>(h13, wo1, wr1, 128,
                                                      bb1, h2, 128, 1);
    gemm_fused_kernel<<<BNT / 128, 256, FUSED_SMEM>>>(h2, wo2, wr2, 128,
                                                      bb2, h13, 128, 1);
    gemm_fused_kernel<<<BNT / 128, 256, FUSED_SMEM>>>(h13, wo3, wr3, 64,
                                                      bb3, H, 64, 0);

    // final bilinear via tf32 tensor cores (symmetric: upper-triangle pairs)
    final_syrk_kernel<<<dim3(136, Bb), 256, SYRK_SMEM>>>(H, out);
}

// round 16
// speedup vs baseline: 1.6084x; 1.6084x over previous
#include <cuda_runtime.h>
#include <math_constants.h>
#include <cstdint>

#define Bb   16
#define Nn   2048
#define Cc   10
#define KK   16
#define BNT  (Bb*Nn)        // 32768 nodes
#define EDG  (BNT*KK)       // 524288 edges

// ---------------- scratch (device globals: no allocation allowed) ----------
__device__ int   g_nbr[EDG];
__device__ int   g_deg[BNT];
__device__ int   g_off[BNT];
__device__ int   g_cur[BNT];
__device__ int   g_rev[EDG];
__device__ float g_h [BNT*128];     // Acat0 (stride 20)
__device__ float g_hb[BNT*128];     // final H (stride 64)
__device__ float g_a [BNT*256];     // h1 / h3 (stride 128)
__device__ float g_b [BNT*256];     // h2 (stride 128)

// ---------------- kNN v3: 2 threads per query (parity-split candidates) ----
// Block = 256 threads covering 128 consecutive query points of one batch.
// Thread t handles query (t&127); half (t>>7) scans j-groups 8g + 4*half.
// Each half keeps its own 16-best; halves merged at the end (each half sees
// 1024 candidates >> 16, so both lists are full and the merge is exact).
__global__ void __launch_bounds__(256) knn_kernel(const float* __restrict__ x) {
    __shared__ float sn[Nn];
    __shared__ float sd[KK][256];
    __shared__ int   si[KK][256];
    int t    = threadIdx.x;
    int qi   = t & 127;
    int half = t >> 7;
    int node = blockIdx.x * 128 + qi;
    int b    = node >> 11;
    int i    = node & 2047;
    const float*  xb  = x + (size_t)b * Nn * Cc;
    const float4* xb4 = (const float4*)xb;

    for (int j = t; j < Nn; j += 256) {
        float s = 0.f;
#pragma unroll
        for (int c = 0; c < Cc; c++) { float v = xb[j * Cc + c]; s = fmaf(v, v, s); }
        sn[j] = s;
    }
    float xi[Cc];
#pragma unroll
    for (int c = 0; c < Cc; c++) xi[c] = xb[i * Cc + c];
#pragma unroll
    for (int r = 0; r < KK; r++) { sd[r][t] = CUDART_INF_F; si[r][t] = 0; }
    __syncthreads();
    float x2i = sn[i];

    float cut = CUDART_INF_F;
    int   cutpos = 0;

    for (int j0 = half * 4; j0 < Nn; j0 += 8) {
        float v[40];
#pragma unroll
        for (int q = 0; q < 10; q++) {
            float4 t4 = xb4[(j0 * 10) / 4 + q];
            v[q*4+0] = t4.x; v[q*4+1] = t4.y; v[q*4+2] = t4.z; v[q*4+3] = t4.w;
        }
#pragma unroll
        for (int jj = 0; jj < 4; jj++) {
            int j = j0 + jj;
            float dot = 0.f;
#pragma unroll
            for (int c = 0; c < Cc; c++) dot = fmaf(xi[c], v[jj * 10 + c], dot);
            float d2 = fmaf(-2.f, dot, x2i + sn[j]);
            if (j != i && d2 < cut) {
                sd[cutpos][t] = d2; si[cutpos][t] = j;
                float m = sd[0][t]; int mp = 0;
#pragma unroll
                for (int r = 1; r < KK; r++) {
                    float dr = sd[r][t];
                    if (dr > m) { m = dr; mp = r; }
                }
                cut = m; cutpos = mp;
            }
        }
    }
    __syncthreads();

    if (half == 0) {
        // merge partner's 16 into own list via same replace-max insert
#pragma unroll
        for (int r = 0; r < KK; r++) {
            float d2 = sd[r][t + 128];
            int   j  = si[r][t + 128];
            if (d2 < cut) {
                sd[cutpos][t] = d2; si[cutpos][t] = j;
                float m = sd[0][t]; int mp = 0;
#pragma unroll
                for (int rr = 1; rr < KK; rr++) {
                    float dr = sd[rr][t];
                    if (dr > m) { m = dr; mp = rr; }
                }
                cut = m; cutpos = mp;
            }
        }
        int base = node * KK;
#pragma unroll
        for (int r = 0; r < KK; r++) {
            int nb = (b << 11) + si[r][t];
            g_nbr[base + r] = nb;
            atomicAdd(&g_deg[nb], 1);
        }
    }
}

// ---------------- exclusive scan v3: 32 elems/thread, one pass --------------
__global__ void scan_kernel() {
    __shared__ int wsum[32];
    int t = threadIdx.x, lane = t & 31, w = t >> 5;
    int base_i = t * 32;
    int loc[32];
    int s = 0;
#pragma unroll
    for (int q = 0; q < 8; q++) {
        int4 v = *(const int4*)&g_deg[base_i + q * 4];
        loc[q*4+0] = s; s += v.x;
        loc[q*4+1] = s; s += v.y;
        loc[q*4+2] = s; s += v.z;
        loc[q*4+3] = s; s += v.w;
    }
    int inc = s;
#pragma unroll
    for (int o = 1; o < 32; o <<= 1) {
        int n = __shfl_up_sync(0xffffffffu, inc, o);
        if (lane >= o) inc += n;
    }
    if (lane == 31) wsum[w] = inc;
    __syncthreads();
    if (w == 0) {
        int v2 = wsum[lane];
#pragma unroll
        for (int o = 1; o < 32; o <<= 1) {
            int n = __shfl_up_sync(0xffffffffu, v2, o);
            if (lane >= o) v2 += n;
        }
        wsum[lane] = v2;
    }
    __syncthreads();
    int base = ((w > 0) ? wsum[w - 1] : 0) + inc - s;
#pragma unroll
    for (int q = 0; q < 8; q++) {
        int4 o4 = make_int4(base + loc[q*4+0], base + loc[q*4+1],
                            base + loc[q*4+2], base + loc[q*4+3]);
        *(int4*)&g_off[base_i + q * 4] = o4;
        *(int4*)&g_cur[base_i + q * 4] = o4;
    }
}

__global__ void fill_kernel() {
    int e = blockIdx.x * blockDim.x + threadIdx.x;
    if (e >= EDG) return;
    int i = e >> 4;
    int v = g_nbr[e];
    int pos = atomicAdd(&g_cur[v], 1);
    g_rev[pos] = i;
}

// ---------------- layer-0 concat: Acat0[v] = [x_v (10) | sum x_u (10)] -----
__global__ void aggx_kernel(const float* __restrict__ x, float* __restrict__ acat) {
    int warp = threadIdx.x >> 5, lane = threadIdx.x & 31;
    int v = blockIdx.x * 8 + warp;
    float xv = 0.f;
    if (lane < 10) xv = x[(size_t)v * 10 + lane];
    int s = g_off[v];
    int e = s + g_deg[v];
    float a0 = 0.f, a1 = 0.f, a2 = 0.f, a3 = 0.f;
    int q = s;
    for (; q + 4 <= e; q += 4) {
        int u0 = __ldg(&g_rev[q]);
        int u1 = __ldg(&g_rev[q + 1]);
        int u2 = __ldg(&g_rev[q + 2]);
        int u3 = __ldg(&g_rev[q + 3]);
        if (lane < 10) {
            a0 += x[(size_t)u0 * 10 + lane];
            a1 += x[(size_t)u1 * 10 + lane];
            a2 += x[(size_t)u2 * 10 + lane];
            a3 += x[(size_t)u3 * 10 + lane];
        }
    }
    for (; q < e; q++) {
        int u = __ldg(&g_rev[q]);
        if (lane < 10) a0 += x[(size_t)u * 10 + lane];
    }
    float acc = (a0 + a1) + (a2 + a3);
    if (lane < 10) {
        acat[(size_t)v * 20 + lane]      = xv;
        acat[(size_t)v * 20 + 10 + lane] = acc;
    }
}

// ---------------- tf32 helpers ----------------------------------------------
__device__ __forceinline__ float f2tf_f(float f) {
    uint32_t u;
    asm("cvt.rna.tf32.f32 %0, %1;" : "=r"(u) : "f"(f));
    return __uint_as_float(u);
}
__device__ __forceinline__ uint32_t f2tf(float f) {
    uint32_t u;
    asm("cvt.rna.tf32.f32 %0, %1;" : "=r"(u) : "f"(f));
    return u;
}

#define GLDA 17

// ---------------- generic tf32 GEMM (layer 0): Out = relu(A@[wo;wr]+b) ------
__global__ void __launch_bounds__(256, 2) gemm_tf32_kernel(
        const float* __restrict__ A, int lda, int K, int Khalf,
        const float* __restrict__ wo, const float* __restrict__ wr, int P,
        const float* __restrict__ bias, float* __restrict__ Out, int ldo,
        int do_relu) {
    __shared__ float As[128 * GLDA];
    __shared__ float Ws[128 * GLDA];
    int bm  = blockIdx.x * 128;
    int tid = threadIdx.x;
    int r2  = tid >> 1;
    int kh  = (tid & 1) * 8;
    int warp = tid >> 5, lane = tid & 31;
    int wm = warp & 3, wn = warp >> 2;
    int g  = lane >> 2, t4 = lane & 3;

    float acc[2][8][4];
#pragma unroll
    for (int mt = 0; mt < 2; mt++)
#pragma unroll
        for (int nt = 0; nt < 8; nt++)
#pragma unroll
            for (int e = 0; e < 4; e++) acc[mt][nt][e] = 0.f;

    for (int k0 = 0; k0 < K; k0 += 16) {
        const float* Ap = &A[(size_t)(bm + r2) * lda + k0 + kh];
        if (k0 + kh + 8 <= K) {
            float4 v0 = *(const float4*)Ap;
            float4 v1 = *(const float4*)(Ap + 4);
            As[r2 * GLDA + kh + 0] = f2tf_f(v0.x);
            As[r2 * GLDA + kh + 1] = f2tf_f(v0.y);
            As[r2 * GLDA + kh + 2] = f2tf_f(v0.z);
            As[r2 * GLDA + kh + 3] = f2tf_f(v0.w);
            As[r2 * GLDA + kh + 4] = f2tf_f(v1.x);
            As[r2 * GLDA + kh + 5] = f2tf_f(v1.y);
            As[r2 * GLDA + kh + 6] = f2tf_f(v1.z);
            As[r2 * GLDA + kh + 7] = f2tf_f(v1.w);
        } else {
#pragma unroll
            for (int q = 0; q < 8; q++) {
                int kk = k0 + kh + q;
                As[r2 * GLDA + kh + q] = (kk < K) ? f2tf_f(Ap[q]) : 0.f;
            }
        }
#pragma unroll
        for (int q = 0; q < 8; q++) {
            int kk = k0 + kh + q;
            float v = 0.f;
            if (kk < K && r2 < P)
                v = (kk < Khalf) ? wo[(size_t)kk * P + r2]
                                 : wr[(size_t)(kk - Khalf) * P + r2];
            Ws[r2 * GLDA + kh + q] = f2tf_f(v);
        }
        __syncthreads();
#pragma unroll
        for (int ks = 0; ks < 16; ks += 8) {
            uint32_t a[2][4], bfr[8][2];
#pragma unroll
            for (int mt = 0; mt < 2; mt++) {
                int row = wm * 32 + mt * 16;
                a[mt][0] = __float_as_uint(As[(row + g    ) * GLDA + ks + t4    ]);
                a[mt][1] = __float_as_uint(As[(row + g + 8) * GLDA + ks + t4    ]);
                a[mt][2] = __float_as_uint(As[(row + g    ) * GLDA + ks + t4 + 4]);
                a[mt][3] = __float_as_uint(As[(row + g + 8) * GLDA + ks + t4 + 4]);
            }
#pragma unroll
            for (int nt = 0; nt < 8; nt++) {
                int col = wn * 64 + nt * 8;
                bfr[nt][0] = __float_as_uint(Ws[(col + g) * GLDA + ks + t4    ]);
                bfr[nt][1] = __float_as_uint(Ws[(col + g) * GLDA + ks + t4 + 4]);
            }
#pragma unroll
            for (int mt = 0; mt < 2; mt++)
#pragma unroll
                for (int nt = 0; nt < 8; nt++) {
                    asm volatile(
                        "mma.sync.aligned.m16n8k8.row.col.f32.tf32.tf32.f32 "
                        "{%0,%1,%2,%3}, {%4,%5,%6,%7}, {%8,%9}, {%0,%1,%2,%3};"
                        : "+f"(acc[mt][nt][0]), "+f"(acc[mt][nt][1]),
                          "+f"(acc[mt][nt][2]), "+f"(acc[mt][nt][3])
                        : "r"(a[mt][0]), "r"(a[mt][1]), "r"(a[mt][2]), "r"(a[mt][3]),
                          "r"(bfr[nt][0]), "r"(bfr[nt][1]));
                }
        }
        __syncthreads();
    }

#pragma unroll
    for (int nt = 0; nt < 8; nt++) {
        int col = wn * 64 + nt * 8 + 2 * t4;
        if (col >= P) continue;
        float b0 = bias[col], b1 = bias[col + 1];
#pragma unroll
        for (int mt = 0; mt < 2; mt++) {
            int row = bm + wm * 32 + mt * 16 + g;
            float o0 = acc[mt][nt][0] + b0;
            float o1 = acc[mt][nt][1] + b1;
            float o2 = acc[mt][nt][2] + b0;
            float o3 = acc[mt][nt][3] + b1;
            if (do_relu) {
                o0 = fmaxf(o0, 0.f); o1 = fmaxf(o1, 0.f);
                o2 = fmaxf(o2, 0.f); o3 = fmaxf(o3, 0.f);
            }
            *(float2*)&Out[(size_t)row * ldo + col]       = make_float2(o0, o1);
            *(float2*)&Out[(size_t)(row + 8) * ldo + col] = make_float2(o2, o3);
        }
    }
}

// ---------------- fused gather+GEMM (layers 1-3) -----------------------------
#define FLDT 132
#define FUSED_SMEM ((128 * FLDT + 2 * 128 * GLDA) * 4)

__global__ void __launch_bounds__(256, 2) gemm_fused_kernel(
        const float* __restrict__ h,
        const float* __restrict__ wo, const float* __restrict__ wr, int P,
        const float* __restrict__ bias, float* __restrict__ Out, int ldo,
        int do_relu) {
    extern __shared__ float sm[];
    float* agg = sm;                       // [128][FLDT]
    float* As  = sm + 128 * FLDT;          // [128][GLDA]
    float* Ws  = As + 128 * GLDA;          // [128][GLDA]
    int bm  = blockIdx.x * 128;
    int tid = threadIdx.x;
    int warp = tid >> 5, lane = tid & 31;

    // ---- gather neighbor sums, 4-way unrolled for MLP ----
#pragma unroll 1
    for (int s = 0; s < 16; s++) {
        int r = warp * 16 + s;
        int v = bm + r;
        int c4 = lane * 4;
        int off = g_off[v];
        int deg = g_deg[v];
        float4 a0 = make_float4(0.f, 0.f, 0.f, 0.f);
        float4 a1 = a0, a2 = a0, a3 = a0;
        int q = off, qe = off + deg;
        for (; q + 4 <= qe; q += 4) {
            int u0 = __ldg(&g_rev[q]);
            int u1 = __ldg(&g_rev[q + 1]);
            int u2 = __ldg(&g_rev[q + 2]);
            int u3 = __ldg(&g_rev[q + 3]);
            float4 t0 = *(const float4*)&h[(size_t)u0 * 128 + c4];
            float4 t1 = *(const float4*)&h[(size_t)u1 * 128 + c4];
            float4 t2 = *(const float4*)&h[(size_t)u2 * 128 + c4];
            float4 t3 = *(const float4*)&h[(size_t)u3 * 128 + c4];
            a0.x += t0.x; a0.y += t0.y; a0.z += t0.z; a0.w += t0.w;
            a1.x += t1.x; a1.y += t1.y; a1.z += t1.z; a1.w += t1.w;
            a2.x += t2.x; a2.y += t2.y; a2.z += t2.z; a2.w += t2.w;
            a3.x += t3.x; a3.y += t3.y; a3.z += t3.z; a3.w += t3.w;
        }
        for (; q < qe; q++) {
            int u = __ldg(&g_rev[q]);
            float4 t0 = *(const float4*)&h[(size_t)u * 128 + c4];
            a0.x += t0.x; a0.y += t0.y; a0.z += t0.z; a0.w += t0.w;
        }
        float4 acc;
        acc.x = (a0.x + a1.x) + (a2.x + a3.x);
        acc.y = (a0.y + a1.y) + (a2.y + a3.y);
        acc.z = (a0.z + a1.z) + (a2.z + a3.z);
        acc.w = (a0.w + a1.w) + (a2.w + a3.w);
        float4 ta;
        ta.x = f2tf_f(acc.x); ta.y = f2tf_f(acc.y);
        ta.z = f2tf_f(acc.z); ta.w = f2tf_f(acc.w);
        *(float4*)&agg[r * FLDT + c4] = ta;
    }
    __syncthreads();

    int r2 = tid >> 1;
    int kh = (tid & 1) * 8;
    int wm = warp & 3, wn = warp >> 2;
    int g  = lane >> 2, t4 = lane & 3;

    float acc[2][8][4];
#pragma unroll
    for (int mt = 0; mt < 2; mt++)
#pragma unroll
        for (int nt = 0; nt < 8; nt++)
#pragma unroll
            for (int e = 0; e < 4; e++) acc[mt][nt][e] = 0.f;

    // ---- left K-half: root features from global h (staged) ----
    for (int k0 = 0; k0 < 128; k0 += 16) {
        const float* Ap = &h[(size_t)(bm + r2) * 128 + k0 + kh];
        float4 v0 = *(const float4*)Ap;
        float4 v1 = *(const float4*)(Ap + 4);
        As[r2 * GLDA + kh + 0] = f2tf_f(v0.x);
        As[r2 * GLDA + kh + 1] = f2tf_f(v0.y);
        As[r2 * GLDA + kh + 2] = f2tf_f(v0.z);
        As[r2 * GLDA + kh + 3] = f2tf_f(v0.w);
        As[r2 * GLDA + kh + 4] = f2tf_f(v1.x);
        As[r2 * GLDA + kh + 5] = f2tf_f(v1.y);
        As[r2 * GLDA + kh + 6] = f2tf_f(v1.z);
        As[r2 * GLDA + kh + 7] = f2tf_f(v1.w);
#pragma unroll
        for (int q = 0; q < 8; q++) {
            int kk = k0 + kh + q;
            float v = (r2 < P) ? wo[(size_t)kk * P + r2] : 0.f;
            Ws[r2 * GLDA + kh + q] = f2tf_f(v);
        }
        __syncthreads();
#pragma unroll
        for (int ks = 0; ks < 16; ks += 8) {
            uint32_t a[2][4], bfr[8][2];
#pragma unroll
            for (int mt = 0; mt < 2; mt++) {
                int row = wm * 32 + mt * 16;
                a[mt][0] = __float_as_uint(As[(row + g    ) * GLDA + ks + t4    ]);
                a[mt][1] = __float_as_uint(As[(row + g + 8) * GLDA + ks + t4    ]);
                a[mt][2] = __float_as_uint(As[(row + g    ) * GLDA + ks + t4 + 4]);
                a[mt][3] = __float_as_uint(As[(row + g + 8) * GLDA + ks + t4 + 4]);
            }
#pragma unroll
            for (int nt = 0; nt < 8; nt++) {
                int col = wn * 64 + nt * 8;
                bfr[nt][0] = __float_as_uint(Ws[(col + g) * GLDA + ks + t4    ]);
                bfr[nt][1] = __float_as_uint(Ws[(col + g) * GLDA + ks + t4 + 4]);
            }
#pragma unroll
            for (int mt = 0; mt < 2; mt++)
#pragma unroll
                for (int nt = 0; nt < 8; nt++) {
                    asm volatile(
                        "mma.sync.aligned.m16n8k8.row.col.f32.tf32.tf32.f32 "
                        "{%0,%1,%2,%3}, {%4,%5,%6,%7}, {%8,%9}, {%0,%1,%2,%3};"
                        : "+f"(acc[mt][nt][0]), "+f"(acc[mt][nt][1]),
                          "+f"(acc[mt][nt][2]), "+f"(acc[mt][nt][3])
                        : "r"(a[mt][0]), "r"(a[mt][1]), "r"(a[mt][2]), "r"(a[mt][3]),
                          "r"(bfr[nt][0]), "r"(bfr[nt][1]));
                }
        }
        __syncthreads();
    }

    // ---- right K-half: aggregated features from smem (direct fragments) ----
    for (int k0 = 0; k0 < 128; k0 += 16) {
#pragma unroll
        for (int q = 0; q < 8; q++) {
            int kk = k0 + kh + q;
            float v = (r2 < P) ? wr[(size_t)kk * P + r2] : 0.f;
            Ws[r2 * GLDA + kh + q] = f2tf_f(v);
        }
        __syncthreads();
#pragma unroll
        for (int ks = 0; ks < 16; ks += 8) {
            int kb = k0 + ks;
            uint32_t a[2][4], bfr[8][2];
#pragma unroll
            for (int mt = 0; mt < 2; mt++) {
                int row = wm * 32 + mt * 16;
                a[mt][0] = __float_as_uint(agg[(row + g    ) * FLDT + kb + t4    ]);
                a[mt][1] = __float_as_uint(agg[(row + g + 8) * FLDT + kb + t4    ]);
                a[mt][2] = __float_as_uint(agg[(row + g    ) * FLDT + kb + t4 + 4]);
                a[mt][3] = __float_as_uint(agg[(row + g + 8) * FLDT + kb + t4 + 4]);
            }
#pragma unroll
            for (int nt = 0; nt < 8; nt++) {
                int col = wn * 64 + nt * 8;
                bfr[nt][0] = __float_as_uint(Ws[(col + g) * GLDA + ks + t4    ]);
                bfr[nt][1] = __float_as_uint(Ws[(col + g) * GLDA + ks + t4 + 4]);
            }
#pragma unroll
            for (int mt = 0; mt < 2; mt++)
#pragma unroll
                for (int nt = 0; nt < 8; nt++) {
                    asm volatile(
                        "mma.sync.aligned.m16n8k8.row.col.f32.tf32.tf32.f32 "
                        "{%0,%1,%2,%3}, {%4,%5,%6,%7}, {%8,%9}, {%0,%1,%2,%3};"
                        : "+f"(acc[mt][nt][0]), "+f"(acc[mt][nt][1]),
                          "+f"(acc[mt][nt][2]), "+f"(acc[mt][nt][3])
                        : "r"(a[mt][0]), "r"(a[mt][1]), "r"(a[mt][2]), "r"(a[mt][3]),
                          "r"(bfr[nt][0]), "r"(bfr[nt][1]));
                }
        }
        __syncthreads();
    }

    // ---- epilogue: bias + optional relu ----
#pragma unroll
    for (int nt = 0; nt < 8; nt++) {
        int col = wn * 64 + nt * 8 + 2 * t4;
        if (col >= P) continue;
        float b0 = bias[col], b1 = bias[col + 1];
#pragma unroll
        for (int mt = 0; mt < 2; mt++) {
            int row = bm + wm * 32 + mt * 16 + g;
            float o0 = acc[mt][nt][0] + b0;
            float o1 = acc[mt][nt][1] + b1;
            float o2 = acc[mt][nt][2] + b0;
            float o3 = acc[mt][nt][3] + b1;
            if (do_relu) {
                o0 = fmaxf(o0, 0.f); o1 = fmaxf(o1, 0.f);
                o2 = fmaxf(o2, 0.f); o3 = fmaxf(o3, 0.f);
            }
            *(float2*)&Out[(size_t)row * ldo + col]       = make_float2(o0, o1);
            *(float2*)&Out[(size_t)(row + 8) * ldo + col] = make_float2(o2, o3);
        }
    }
}

// ---------------- final syrk (tf32 tensor cores, symmetric) ------------------
#define SYRK_LD  68
#define SYRK_SMEM (2 * 128 * SYRK_LD * 4)
#define TLDT 129

__global__ void __launch_bounds__(256, 2) final_syrk_kernel(
        const float* __restrict__ H, float* __restrict__ out) {
    extern __shared__ float smem[];
    float* As = smem;
    float* Bs = smem + 128 * SYRK_LD;
    int b = blockIdx.y;

    int r = blockIdx.x, bi = 0;
    while (r >= 16 - bi) { r -= 16 - bi; bi++; }
    int bj = bi + r;
    int i0 = bi * 128;
    int j0 = bj * 128;

    const float* Hb = H + (size_t)b * Nn * 64;
    int tid = threadIdx.x;

#pragma unroll
    for (int q = 0; q < 8; q++) {
        int f = q * 256 + tid;
        int rr = f >> 4;
        int c = (f & 15) * 4;
        float4 va = *(const float4*)&Hb[(size_t)(i0 + rr) * 64 + c];
        float4 vb = *(const float4*)&Hb[(size_t)(j0 + rr) * 64 + c];
        float4 ta, tb;
        ta.x = __uint_as_float(f2tf(va.x)); ta.y = __uint_as_float(f2tf(va.y));
        ta.z = __uint_as_float(f2tf(va.z)); ta.w = __uint_as_float(f2tf(va.w));
        tb.x = __uint_as_float(f2tf(vb.x)); tb.y = __uint_as_float(f2tf(vb.y));
        tb.z = __uint_as_float(f2tf(vb.z)); tb.w = __uint_as_float(f2tf(vb.w));
        *(float4*)&As[rr * SYRK_LD + c] = ta;
        *(float4*)&Bs[rr * SYRK_LD + c] = tb;
    }
    __syncthreads();

    int warp = tid >> 5, lane = tid & 31;
    int wm = warp & 3;
    int wn = warp >> 2;
    int g  = lane >> 2;
    int t  = lane & 3;

    float acc[2][8][4];
#pragma unroll
    for (int mt = 0; mt < 2; mt++)
#pragma unroll
        for (int nt = 0; nt < 8; nt++)
#pragma unroll
            for (int e = 0; e < 4; e++) acc[mt][nt][e] = 0.f;

#pragma unroll
    for (int ks = 0; ks < 8; ks++) {
        int k0 = ks * 8;
        uint32_t a[2][4], bf[8][2];
#pragma unroll
        for (int mt = 0; mt < 2; mt++) {
            int row = wm * 32 + mt * 16;
            a[mt][0] = __float_as_uint(As[(row + g    ) * SYRK_LD + k0 + t    ]);
            a[mt][1] = __float_as_uint(As[(row + g + 8) * SYRK_LD + k0 + t    ]);
            a[mt][2] = __float_as_uint(As[(row + g    ) * SYRK_LD + k0 + t + 4]);
            a[mt][3] = __float_as_uint(As[(row + g + 8) * SYRK_LD + k0 + t + 4]);
        }
#pragma unroll
        for (int nt = 0; nt < 8; nt++) {
            int col = wn * 64 + nt * 8;
            bf[nt][0] = __float_as_uint(Bs[(col + g) * SYRK_LD + k0 + t    ]);
            bf[nt][1] = __float_as_uint(Bs[(col + g) * SYRK_LD + k0 + t + 4]);
        }
#pragma unroll
        for (int mt = 0; mt < 2; mt++)
#pragma unroll
            for (int nt = 0; nt < 8; nt++) {
                asm volatile(
                    "mma.sync.aligned.m16n8k8.row.col.f32.tf32.tf32.f32 "
                    "{%0,%1,%2,%3}, {%4,%5,%6,%7}, {%8,%9}, {%0,%1,%2,%3};"
                    : "+f"(acc[mt][nt][0]), "+f"(acc[mt][nt][1]),
                      "+f"(acc[mt][nt][2]), "+f"(acc[mt][nt][3])
                    : "r"(a[mt][0]), "r"(a[mt][1]), "r"(a[mt][2]), "r"(a[mt][3]),
                      "r"(bf[nt][0]), "r"(bf[nt][1]));
            }
    }

    float* ob = out + (size_t)b * Nn * Nn;

#pragma unroll
    for (int mt = 0; mt < 2; mt++)
#pragma unroll
        for (int nt = 0; nt < 8; nt++) {
            int row = i0 + wm * 32 + mt * 16 + g;
            int col = j0 + wn * 64 + nt * 8 + 2 * t;
            float2 lo = make_float2(acc[mt][nt][0], acc[mt][nt][1]);
            float2 hi = make_float2(acc[mt][nt][2], acc[mt][nt][3]);
            *(float2*)&ob[(size_t)row * Nn + col]       = lo;
            *(float2*)&ob[(size_t)(row + 8) * Nn + col] = hi;
        }

    if (bi != bj) {
        __syncthreads();
        float* trans = smem;  // [128][TLDT]
#pragma unroll
        for (int mt = 0; mt < 2; mt++)
#pragma unroll
            for (int nt = 0; nt < 8; nt++) {
                int r0 = wm * 32 + mt * 16 + g;
                int c0 = wn * 64 + nt * 8 + 2 * t;
                trans[r0 * TLDT + c0]           = acc[mt][nt][0];
                trans[r0 * TLDT + c0 + 1]       = acc[mt][nt][1];
                trans[(r0 + 8) * TLDT + c0]     = acc[mt][nt][2];
                trans[(r0 + 8) * TLDT + c0 + 1] = acc[mt][nt][3];
            }
        __syncthreads();
#pragma unroll 1
        for (int s = 0; s < 16; s++) {
            int jr = warp * 16 + s;
#pragma unroll
            for (int q = 0; q < 4; q++) {
                int ic = q * 32 + lane;
                float v = trans[ic * TLDT + jr];
                ob[(size_t)(j0 + jr) * Nn + i0 + ic] = v;
            }
        }
    }
}

// ---------------- launch ----------------------------------------------------
extern "C" void kernel_launch(void* const* d_in, const int* in_sizes, int n_in,
                              void* d_out, int out_size) {
    const float* x   = (const float*)d_in[0];
    const float* wr0 = (const float*)d_in[1];
    const float* wo0 = (const float*)d_in[2];
    const float* bb0 = (const float*)d_in[3];
    const float* wr1 = (const float*)d_in[4];
    const float* wo1 = (const float*)d_in[5];
    const float* bb1 = (const float*)d_in[6];
    const float* wr2 = (const float*)d_in[7];
    const float* wo2 = (const float*)d_in[8];
    const float* bb2 = (const float*)d_in[9];
    const float* wr3 = (const float*)d_in[10];
    const float* wo3 = (const float*)d_in[11];
    const float* bb3 = (const float*)d_in[12];
    float* out = (float*)d_out;

    float *acat0, *H, *h13, *h2;
    int *degp;
    cudaGetSymbolAddress((void**)&acat0, g_h);
    cudaGetSymbolAddress((void**)&H,     g_hb);
    cudaGetSymbolAddress((void**)&h13,   g_a);
    cudaGetSymbolAddress((void**)&h2,    g_b);
    cudaGetSymbolAddress((void**)&degp,  g_deg);

    cudaFuncSetAttribute(final_syrk_kernel,
                         cudaFuncAttributeMaxDynamicSharedMemorySize, SYRK_SMEM);
    cudaFuncSetAttribute(gemm_fused_kernel,
                         cudaFuncAttributeMaxDynamicSharedMemorySize, FUSED_SMEM);

    // graph construction
    cudaMemsetAsync(degp, 0, BNT * sizeof(int), 0);
    knn_kernel<<<BNT / 128, 256>>>(x);
    scan_kernel<<<1, 1024>>>();
    fill_kernel<<<(EDG + 255) / 256, 256>>>();

    // layer 0: Acat0 = [x | agg(x)] (K=20) -> h1 [BNT][128]
    aggx_kernel<<<BNT / 8, 256>>>(x, acat0);
    gemm_tf32_kernel<<<BNT / 128, 256>>>(acat0, 20, 20, 10, wo0, wr0, 128,
                                         bb0, h13, 128, 1);
    // layers 1-3: fused gather + GEMM
    gemm_fused_kernel<<<BNT / 128, 256, FUSED_SMEM>>>(h13, wo1, wr1, 128,
                                                      bb1, h2, 128, 1);
    gemm_fused_kernel<<<BNT / 128, 256, FUSED_SMEM>>>(h2, wo2, wr2, 128,
                                                      bb2, h13, 128, 1);
    gemm_fused_kernel<<<BNT / 128, 256, FUSED_SMEM>>>(h13, wo3, wr3, 64,
                                                      bb3, H, 64, 0);

    // final bilinear via tf32 tensor cores (symmetric: upper-triangle pairs)
    final_syrk_kernel<<<dim3(136, Bb), 256, SYRK_SMEM>>>(H, out);
}